// round 16
// baseline (speedup 1.0000x reference)
#include <cuda_runtime.h>
#include <cuda_fp16.h>
#include <math.h>
#include <stdint.h>

#define NN   2048
#define RR   5
#define CC   2
#define DD   256
#define HD   128
#define NCLS 16
#define KS   4          // split-K factor for X gemm

// ---------------- scratch (device globals, no allocations) ----------------
__device__ float g_F[6 * RR];
__device__ float g_part[CC * 16 * NN];
__device__ float g_deg [CC * NN];
__device__ float g_Xp[KS * CC * NN * HD];   // split-K partials of X
__device__ float g_X  [CC * NN * HD];
__device__ float g_X2 [NN * HD];
__device__ __half g_Q0f[CC * NN * NN];
__device__ __half g_Q1t[CC * NN * NN];
__device__ __half g_Q2t[CC * NN * NN];
__device__ __half g_H16 [CC * NN * NN];     // GEMM1 out (fp16)
__device__ __half g_Hf  [CC * NN * NN];     // normalized H (A of GEMM2)
__device__ __half g_H216[CC * NN * NN];     // GEMM2 out (fp16)
__device__ __half g_HsT [CC * NN * NN];     // A of X gemm
__device__ __half g_hWT [HD * NN];          // B of X gemm: hWT[d][n] = (h@gcn_w)[n][d]

// ================= PTX helpers =================
__device__ __forceinline__ uint32_t smem_u32(const void* p) {
    uint32_t a;
    asm("{ .reg .u64 t; cvta.to.shared.u64 t, %1; cvt.u32.u64 %0, t; }" : "=r"(a) : "l"(p));
    return a;
}
__device__ __forceinline__ void cpasync16(uint32_t dst, const void* src) {
    asm volatile("cp.async.cg.shared.global [%0], [%1], 16;" :: "r"(dst), "l"(src) : "memory");
}
__device__ __forceinline__ void cpasync_commit() {
    asm volatile("cp.async.commit_group;" ::: "memory");
}
template<int N> __device__ __forceinline__ void cpasync_wait() {
    asm volatile("cp.async.wait_group %0;" :: "n"(N) : "memory");
}
__device__ __forceinline__ void ldmx4(uint32_t* r, uint32_t a) {
    asm volatile("ldmatrix.sync.aligned.m8n8.x4.shared.b16 {%0,%1,%2,%3},[%4];"
        : "=r"(r[0]), "=r"(r[1]), "=r"(r[2]), "=r"(r[3]) : "r"(a));
}
__device__ __forceinline__ void mma16(float* c, const uint32_t* a, const uint32_t* b) {
    asm volatile("mma.sync.aligned.m16n8k16.row.col.f32.f16.f16.f32 "
        "{%0,%1,%2,%3},{%4,%5,%6,%7},{%8,%9},{%0,%1,%2,%3};"
        : "+f"(c[0]), "+f"(c[1]), "+f"(c[2]), "+f"(c[3])
        : "r"(a[0]), "r"(a[1]), "r"(a[2]), "r"(a[3]), "r"(b[0]), "r"(b[1]));
}

// ================= fp16 tensor-core GEMM =================
// C[M,N] = A[M,K] * B[N,K]^T, lda=ldb=NN. CTA tile 128x128, 4 warps (64x64 each),
// BK=64, 3-stage cp.async, ONE barrier per k-iteration.
// COLSUM: fused per-tile column sums -> g_part.  HALF: fp16 C output.
#define STAGES  3
#define STG_SZ  32768
#define SMEM16  (STAGES * STG_SZ)

template<bool COLSUM, bool HALF>
__global__ __launch_bounds__(128, 2) void gemm16_k(
    const __half* __restrict__ Ag, const __half* __restrict__ Bg,
    void* __restrict__ Cp, int ldc, long sA, long sB, long sC,
    int cmod, int ktn)
{
    extern __shared__ char smem[];
    const uint32_t sb = smem_u32(smem);
    const int tid = threadIdx.x, lane = tid & 31, warp = tid >> 5;
    const int m0 = blockIdx.y * 128, n0 = blockIdx.x * 128;
    const int z = blockIdx.z;
    const int c = cmod ? (z % cmod) : z;
    const int kt0 = cmod ? (z / cmod) * ktn : 0;
    Ag += (long)c * sA;
    Bg += (long)c * sB;
    const int wm = (warp >> 1) * 64;
    const int wn = (warp & 1) * 64;

    float acc[4][8][4];
    #pragma unroll
    for (int i = 0; i < 4; i++)
        #pragma unroll
        for (int j = 0; j < 8; j++)
            #pragma unroll
            for (int v = 0; v < 4; v++) acc[i][j][v] = 0.f;

    auto load_stage = [&](int st, int k0) {
        const uint32_t sa = sb + st * STG_SZ;
        const uint32_t sbm = sa + 16384;
        #pragma unroll
        for (int i = 0; i < 8; i++) {
            int id = i * 128 + tid;              // 0..1023
            int row = id >> 3, cc = id & 7;
            uint32_t off = (uint32_t)row * 128 + (uint32_t)((cc ^ (row & 7)) << 4);
            cpasync16(sa + off, Ag + (long)(m0 + row) * NN + k0 + cc * 8);
            cpasync16(sbm + off, Bg + (long)(n0 + row) * NN + k0 + cc * 8);
        }
        cpasync_commit();
    };

    #pragma unroll
    for (int s = 0; s < STAGES - 1; s++) load_stage(s, (kt0 + s) * 64);

    int cs = 0, ns = STAGES - 1;
    for (int it = 0; it < ktn; it++) {
        if (it < ktn - 1) cpasync_wait<STAGES - 2>();
        else              cpasync_wait<0>();
        // Single barrier per iteration: guarantees (a) stage cs data visible to
        // all warps, (b) every warp finished computing on stage cs-1 (the next
        // load target) because that compute precedes this barrier in program
        // order. The old trailing barrier was redundant.
        __syncthreads();
        const int kn = it + STAGES - 1;
        if (kn < ktn) {
            load_stage(ns, (kt0 + kn) * 64);
            if (++ns == STAGES) ns = 0;
        }

        const uint32_t sa = sb + cs * STG_SZ;
        const uint32_t sbm = sa + 16384;
        if (++cs == STAGES) cs = 0;

        // register double-buffered fragment pipeline over kk = 0..3
        uint32_t a[2][4][4], b[2][4][4];
        auto ldfrags = [&](int buf, int kk) {
            #pragma unroll
            for (int mi = 0; mi < 4; mi++) {
                int row = wm + mi * 16 + (lane & 15);
                int cc = kk * 2 + (lane >> 4);
                ldmx4(a[buf][mi], sa + row * 128 + ((cc ^ (row & 7)) << 4));
            }
            #pragma unroll
            for (int p = 0; p < 4; p++) {
                int row = wn + p * 16 + (lane & 7) + ((lane >> 4) << 3);
                int cc = kk * 2 + ((lane >> 3) & 1);
                ldmx4(b[buf][p], sbm + row * 128 + ((cc ^ (row & 7)) << 4));
            }
        };
        ldfrags(0, 0);
        #pragma unroll
        for (int kk = 0; kk < 4; kk++) {
            if (kk < 3) ldfrags((kk + 1) & 1, kk + 1);
            const int cur = kk & 1;
            #pragma unroll
            for (int mi = 0; mi < 4; mi++)
                #pragma unroll
                for (int p = 0; p < 4; p++) {
                    mma16(acc[mi][p * 2],     a[cur][mi], &b[cur][p][0]);
                    mma16(acc[mi][p * 2 + 1], a[cur][mi], &b[cur][p][2]);
                }
        }
    }

    // ---- store C ----
    #pragma unroll
    for (int mi = 0; mi < 4; mi++) {
        #pragma unroll
        for (int ni = 0; ni < 8; ni++) {
            int r0 = m0 + wm + mi * 16 + (lane >> 2);
            int c0 = n0 + wn + ni * 8 + (lane & 3) * 2;
            if (HALF) {
                __half* Ch = (__half*)Cp + (long)z * sC;
                *(__half2*)&Ch[(long)r0 * ldc + c0] =
                    __floats2half2_rn(acc[mi][ni][0], acc[mi][ni][1]);
                *(__half2*)&Ch[(long)(r0 + 8) * ldc + c0] =
                    __floats2half2_rn(acc[mi][ni][2], acc[mi][ni][3]);
            } else {
                float* Cf = (float*)Cp + (long)z * sC;
                float2 v0; v0.x = acc[mi][ni][0]; v0.y = acc[mi][ni][1];
                float2 v1; v1.x = acc[mi][ni][2]; v1.y = acc[mi][ni][3];
                *(float2*)&Cf[(long)r0 * ldc + c0]       = v0;
                *(float2*)&Cf[(long)(r0 + 8) * ldc + c0] = v1;
            }
        }
    }

    // ---- fused per-tile column sums (deterministic) ----
    if (COLSUM) {
        float* cs2 = (float*)smem;               // [2][128]
        __syncthreads();                         // stage smem no longer needed
        #pragma unroll
        for (int ni = 0; ni < 8; ni++) {
            #pragma unroll
            for (int j = 0; j < 2; j++) {
                float s = 0.f;
                #pragma unroll
                for (int mi = 0; mi < 4; mi++)
                    s += acc[mi][ni][j] + acc[mi][ni][2 + j];
                s += __shfl_xor_sync(0xFFFFFFFF, s, 4);
                s += __shfl_xor_sync(0xFFFFFFFF, s, 8);
                s += __shfl_xor_sync(0xFFFFFFFF, s, 16);
                if (lane < 4)
                    cs2[(wm >> 6) * 128 + wn + ni * 8 + (lane & 3) * 2 + j] = s;
            }
        }
        __syncthreads();
        if (tid < 128) {
            float tot = cs2[tid] + cs2[128 + tid];
            g_part[(long)c * 16 * NN + (long)blockIdx.y * NN + n0 + tid] = tot;
        }
    }
}

// ---------------- softmax over relations ----------------
__global__ void softmax_k(const float* __restrict__ W) {
    int t = threadIdx.x;
    if (t < 6) {
        const float* w = W + t * RR;
        float mx = w[0];
        #pragma unroll
        for (int r = 1; r < RR; r++) mx = fmaxf(mx, w[r]);
        float e[RR], s = 0.f;
        #pragma unroll
        for (int r = 0; r < RR; r++) { e[r] = expf(w[r] - mx); s += e[r]; }
        #pragma unroll
        for (int r = 0; r < RR; r++) g_F[t * RR + r] = e[r] / s;
    }
}

// ------- fused qcombine + transpose ----------
__global__ __launch_bounds__(256) void qcombine_t_k(const float* __restrict__ A) {
    __shared__ float t[RR][32][33];
    const int x0 = blockIdx.x * 32, y0 = blockIdx.y * 32;
    const int tx = threadIdx.x & 31, ty = threadIdx.x >> 5;
    #pragma unroll
    for (int r = 0; r < RR; r++)
        #pragma unroll
        for (int i = 0; i < 4; i++)
            t[r][ty + 8 * i][tx] = A[(long)r * NN * NN + (long)(y0 + ty + 8 * i) * NN + x0 + tx];
    __syncthreads();

    float f[6][RR];
    #pragma unroll
    for (int c = 0; c < 6; c++)
        #pragma unroll
        for (int r = 0; r < RR; r++) f[c][r] = g_F[c * RR + r];

    #pragma unroll
    for (int c = 0; c < 2; c++)
        #pragma unroll
        for (int i = 0; i < 4; i++) {
            int row = ty + 8 * i;
            float v = 0.f;
            #pragma unroll
            for (int r = 0; r < RR; r++) v = fmaf(f[c][r], t[r][row][tx], v);
            g_Q0f[(long)c * NN * NN + (long)(y0 + row) * NN + x0 + tx] = __float2half_rn(v);
        }
    #pragma unroll
    for (int c = 2; c < 6; c++) {
        __half* dst = (c < 4 ? g_Q1t : g_Q2t) + (long)(c & 1) * NN * NN;
        #pragma unroll
        for (int i = 0; i < 4; i++) {
            int rr = ty + 8 * i;
            float v = 0.f;
            #pragma unroll
            for (int r = 0; r < RR; r++) v = fmaf(f[c][r], t[r][tx][rr], v);
            dst[(long)(x0 + rr) * NN + y0 + tx] = __float2half_rn(v);
        }
    }
}

// ------- hW = h @ gcn_w, written transposed fp16: hWT[d][n] ----------
__global__ __launch_bounds__(256) void hw_t_k(const float* __restrict__ h,
                                              const float* __restrict__ w) {
    __shared__ float hs[32][257];
    const int n0 = blockIdx.x * 32, d0 = blockIdx.y * 32;
    const int tid = threadIdx.x;
    for (int idx = tid; idx < 32 * 256; idx += 256) {
        int n = idx >> 8, k = idx & 255;
        hs[n][k] = h[(long)(n0 + n) * DD + k];
    }
    __syncthreads();
    const int tx = tid & 31, ty = tid >> 5;       // tx: n, ty+8i: d
    float acc[4] = {0.f, 0.f, 0.f, 0.f};
    for (int k = 0; k < DD; k++) {
        float hv = hs[tx][k];
        #pragma unroll
        for (int i = 0; i < 4; i++)
            acc[i] = fmaf(hv, w[k * HD + d0 + ty + 8 * i], acc[i]);
    }
    #pragma unroll
    for (int i = 0; i < 4; i++)
        g_hWT[(long)(d0 + ty + 8 * i) * NN + n0 + tx] = __float2half_rn(acc[i]);
}

// ---------------- colsum final (g_part -> g_deg) ----------------
__global__ __launch_bounds__(128) void colsum_final_k(const __half* __restrict__ H) {
    int idx = blockIdx.x * blockDim.x + threadIdx.x;
    if (idx >= CC * NN) return;
    int c = idx / NN, m = idx % NN;
    float s = 0.f;
    #pragma unroll
    for (int j = 0; j < 16; j++)
        s += g_part[(long)c * 16 * NN + (long)j * NN + m];
    s -= __half2float(H[(long)c * NN * NN + (long)m * NN + m]);
    g_deg[idx] = s;
}

// ---------------- mid norm (fp16 in -> fp16 out) ----------------
__global__ __launch_bounds__(256) void norm_mid_k(const __half* __restrict__ H) {
    long i = (long)blockIdx.x * blockDim.x + threadIdx.x;
    if (i >= (long)CC * NN * NN) return;
    int c = (int)(i / ((long)NN * NN));
    long rem = i % ((long)NN * NN);
    int n = (int)(rem / NN), m = (int)(rem % NN);
    float d = g_deg[c * NN + m];
    float v = (n == m || d <= 0.f) ? 0.f : __half2float(H[i]) / d;
    g_Hf[i] = __float2half_rn(v);
}

// ------- final double norm fused with transpose -> fp16 HsT ----
__global__ __launch_bounds__(256) void norm_final_t_k(const __half* __restrict__ H) {
    __shared__ float t[32][33];
    const int c = blockIdx.z;
    const int x0 = blockIdx.x * 32, y0 = blockIdx.y * 32;
    const int tx = threadIdx.x & 31, ty = threadIdx.x >> 5;
    const float d1 = g_deg[c * NN + x0 + tx];
    const float inv1 = (d1 > 0.f) ? 1.f / d1 : 0.f;
    const float inv2 = (d1 > 0.f) ? 0.5f : 1.f;
    const __half* Hc = H + (long)c * NN * NN;
    #pragma unroll
    for (int i = 0; i < 4; i++) {
        int n = y0 + ty + 8 * i, m = x0 + tx;
        float v = __half2float(Hc[(long)n * NN + m]);
        v = (n == m) ? 1.f : v * inv1;
        t[ty + 8 * i][tx] = v * inv2;
    }
    __syncthreads();
    __half* dst = g_HsT + (long)c * NN * NN;
    #pragma unroll
    for (int i = 0; i < 4; i++) {
        int rr = ty + 8 * i;
        dst[(long)(x0 + rr) * NN + y0 + tx] = __float2half_rn(t[tx][rr]);
    }
}

// ---------------- split-K reduce + bias + relu -> g_X ----------------
__global__ __launch_bounds__(256) void xreduce_k(const float* __restrict__ bias) {
    long i4 = ((long)blockIdx.x * blockDim.x + threadIdx.x) * 4;
    if (i4 >= (long)CC * NN * HD) return;
    float4 s = *(const float4*)&g_Xp[i4];
    #pragma unroll
    for (int ks = 1; ks < KS; ks++) {
        const float4 v = *(const float4*)&g_Xp[(long)ks * CC * NN * HD + i4];
        s.x += v.x; s.y += v.y; s.z += v.z; s.w += v.w;
    }
    const int d = (int)(i4 & (HD - 1));
    s.x = fmaxf(s.x + bias[d],     0.f);
    s.y = fmaxf(s.y + bias[d + 1], 0.f);
    s.z = fmaxf(s.z + bias[d + 2], 0.f);
    s.w = fmaxf(s.w + bias[d + 3], 0.f);
    *(float4*)&g_X[i4] = s;
}

// ---------------- lin1 / lin2 ----------------
__global__ __launch_bounds__(128) void lin1_k(const float* __restrict__ w,
                                              const float* __restrict__ b) {
    __shared__ float xr[CC * HD];
    int m = blockIdx.x, t = threadIdx.x;
    xr[t]      = g_X[(long)m * HD + t];
    xr[HD + t] = g_X[(long)NN * HD + (long)m * HD + t];
    __syncthreads();
    float acc = b[t];
    #pragma unroll 8
    for (int k = 0; k < CC * HD; k++)
        acc = fmaf(xr[k], w[k * HD + t], acc);
    g_X2[(long)m * HD + t] = fmaxf(acc, 0.f);
}
__global__ __launch_bounds__(128) void lin2_k(const int* __restrict__ idx,
                                              const float* __restrict__ w,
                                              const float* __restrict__ b,
                                              float* __restrict__ y, int ncat) {
    int i = blockIdx.x * blockDim.x + threadIdx.x;
    if (i >= ncat * NCLS) return;
    int row = i / NCLS, j = i % NCLS;
    const float* x = g_X2 + (long)idx[row] * HD;
    float acc = b[j];
    #pragma unroll 8
    for (int k = 0; k < HD; k++)
        acc = fmaf(x[k], w[k * NCLS + j], acc);
    y[i] = acc;
}

// ---------------- launch ----------------
extern "C" void kernel_launch(void* const* d_in, const int* in_sizes, int n_in,
                              void* d_out, int out_size) {
    const float *A = 0, *h = 0, *W_conv = 0, *gcn_w = 0, *gcn_b = 0;
    const float *lin1_w = 0, *lin1_b = 0, *lin2_w = 0, *lin2_b = 0;
    const int* catidx = 0;
    int ncat = 0;
    for (int i = 0; i < n_in; i++) {
        int s = in_sizes[i];
        const void* p = d_in[i];
        if      (s == RR * NN * NN) A = (const float*)p;
        else if (s == NN * DD)      h = (const float*)p;
        else if (s == 3 * CC * RR)  W_conv = (const float*)p;
        else if (s == DD * HD) { if (!gcn_w) gcn_w = (const float*)p; else lin1_w = (const float*)p; }
        else if (s == HD)      { if (!gcn_b) gcn_b = (const float*)p; else lin1_b = (const float*)p; }
        else if (s == HD * NCLS) lin2_w = (const float*)p;
        else if (s == NCLS)      lin2_b = (const float*)p;
        else { catidx = (const int*)p; ncat = s; }
    }
    float* y = (float*)d_out;

    float *Xp;
    __half *Q0f, *Q1t, *Q2t, *H16, *Hf, *H216, *HsT, *hWT;
    cudaGetSymbolAddress((void**)&Xp,   g_Xp);
    cudaGetSymbolAddress((void**)&Q0f,  g_Q0f);
    cudaGetSymbolAddress((void**)&Q1t,  g_Q1t);
    cudaGetSymbolAddress((void**)&Q2t,  g_Q2t);
    cudaGetSymbolAddress((void**)&H16,  g_H16);
    cudaGetSymbolAddress((void**)&Hf,   g_Hf);
    cudaGetSymbolAddress((void**)&H216, g_H216);
    cudaGetSymbolAddress((void**)&HsT,  g_HsT);
    cudaGetSymbolAddress((void**)&hWT,  g_hWT);

    static int smem_set = 0;
    if (!smem_set) {
        cudaFuncSetAttribute((const void*)gemm16_k<true, true>,
                             cudaFuncAttributeMaxDynamicSharedMemorySize, SMEM16);
        cudaFuncSetAttribute((const void*)gemm16_k<false, false>,
                             cudaFuncAttributeMaxDynamicSharedMemorySize, SMEM16);
        smem_set = 1;
    }

    const long NNNN = (long)NN * NN;

    softmax_k<<<1, 32>>>(W_conv);
    qcombine_t_k<<<dim3(NN / 32, NN / 32), 256>>>(A);
    hw_t_k<<<dim3(NN / 32, HD / 32), 256>>>(h, gcn_w);

    // GEMM1: H = Q0 @ Q1^T  (fp16 out + fused tile column sums)
    gemm16_k<true, true><<<dim3(16, 16, CC), 128, SMEM16>>>(
        Q0f, Q1t, H16, NN, NNNN, NNNN, NNNN, 0, 32);
    colsum_final_k<<<CC * NN / 128, 128>>>(H16);
    norm_mid_k<<<(int)(CC * NNNN / 256), 256>>>(H16);

    // GEMM2: H2 = Hn @ Q2^T  (fp16 out + fused tile column sums)
    gemm16_k<true, true><<<dim3(16, 16, CC), 128, SMEM16>>>(
        Hf, Q2t, H216, NN, NNNN, NNNN, NNNN, 0, 32);
    colsum_final_k<<<CC * NN / 128, 128>>>(H216);
    norm_final_t_k<<<dim3(NN / 32, NN / 32, CC), 256>>>(H216);

    // X partials (split-K x4, ktn=8): Xp[ks*CC+c] = HsT[c] @ hWT^T over K-slice
    gemm16_k<false, false><<<dim3(HD / 128, NN / 128, CC * KS), 128, SMEM16>>>(
        HsT, hWT, Xp, HD, NNNN, 0, (long)NN * HD, CC, 32 / KS);
    xreduce_k<<<(int)((long)CC * NN * HD / 4 / 256), 256>>>(gcn_b);

    lin1_k<<<NN, 128>>>(lin1_w, lin1_b);
    lin2_k<<<(ncat * NCLS + 127) / 128, 128>>>(catidx, lin2_w, lin2_b, y, ncat);
}

// round 17
// speedup vs baseline: 1.0090x; 1.0090x over previous
#include <cuda_runtime.h>
#include <cuda_fp16.h>
#include <math.h>
#include <stdint.h>

#define NN   2048
#define RR   5
#define CC   2
#define DD   256
#define HD   128
#define NCLS 16
#define KS   4          // split-K factor for X gemm

// ---------------- scratch (device globals, no allocations) ----------------
__device__ float g_F[6 * RR];
__device__ float g_part[CC * 16 * NN];
__device__ float g_deg [CC * NN];
__device__ float g_Xp[KS * CC * NN * HD];   // split-K partials of X
__device__ float g_X2 [NN * HD];            // lin1 output (fp32)
__device__ __half g_Q0f[CC * NN * NN];
__device__ __half g_Q1t[CC * NN * NN];
__device__ __half g_Q2t[CC * NN * NN];
__device__ __half g_H16 [CC * NN * NN];     // GEMM1 out (fp16)
__device__ __half g_Hf  [CC * NN * NN];     // normalized H (A of GEMM2)
__device__ __half g_H216[CC * NN * NN];     // GEMM2 out (fp16)
__device__ __half g_HsT [CC * NN * NN];     // A of X gemm
__device__ __half g_hWT [HD * NN];          // B of X gemm: hWT[d][n] = (h@gcn_w)[n][d]
__device__ __half g_Xcat[NN * CC * HD];     // concat X fp16: [n][c*HD+d]
__device__ __half g_w1T [HD * CC * HD];     // lin1_w transposed fp16: [d'][k=256]

// ================= PTX helpers =================
__device__ __forceinline__ uint32_t smem_u32(const void* p) {
    uint32_t a;
    asm("{ .reg .u64 t; cvta.to.shared.u64 t, %1; cvt.u32.u64 %0, t; }" : "=r"(a) : "l"(p));
    return a;
}
__device__ __forceinline__ void cpasync16(uint32_t dst, const void* src) {
    asm volatile("cp.async.cg.shared.global [%0], [%1], 16;" :: "r"(dst), "l"(src) : "memory");
}
__device__ __forceinline__ void cpasync_commit() {
    asm volatile("cp.async.commit_group;" ::: "memory");
}
template<int N> __device__ __forceinline__ void cpasync_wait() {
    asm volatile("cp.async.wait_group %0;" :: "n"(N) : "memory");
}
__device__ __forceinline__ void ldmx4(uint32_t* r, uint32_t a) {
    asm volatile("ldmatrix.sync.aligned.m8n8.x4.shared.b16 {%0,%1,%2,%3},[%4];"
        : "=r"(r[0]), "=r"(r[1]), "=r"(r[2]), "=r"(r[3]) : "r"(a));
}
__device__ __forceinline__ void mma16(float* c, const uint32_t* a, const uint32_t* b) {
    asm volatile("mma.sync.aligned.m16n8k16.row.col.f32.f16.f16.f32 "
        "{%0,%1,%2,%3},{%4,%5,%6,%7},{%8,%9},{%0,%1,%2,%3};"
        : "+f"(c[0]), "+f"(c[1]), "+f"(c[2]), "+f"(c[3])
        : "r"(a[0]), "r"(a[1]), "r"(a[2]), "r"(a[3]), "r"(b[0]), "r"(b[1]));
}

// ================= fp16 tensor-core GEMM =================
// C[M,N] = A[M,K] * B[N,K]^T. CTA tile 128x128, 4 warps (64x64 each), BK=64,
// 3-stage cp.async with load issue INTERLEAVED into the kk loop.
// COLSUM: fused per-tile column sums -> g_part.  HALF: fp16 C.  EPI: +bias,relu (fp32 C).
#define STAGES  3
#define STG_SZ  32768
#define SMEM16  (STAGES * STG_SZ)

template<bool COLSUM, bool HALF, bool EPI>
__global__ __launch_bounds__(128, 2) void gemm16_k(
    const __half* __restrict__ Ag, const __half* __restrict__ Bg,
    void* __restrict__ Cp, int lda, int ldb, int ldc,
    long sA, long sB, long sC, int cmod, int ktn,
    const float* __restrict__ bias)
{
    extern __shared__ char smem[];
    const uint32_t sb = smem_u32(smem);
    const int tid = threadIdx.x, lane = tid & 31, warp = tid >> 5;
    const int m0 = blockIdx.y * 128, n0 = blockIdx.x * 128;
    const int z = blockIdx.z;
    const int c = cmod ? (z % cmod) : z;
    const int kt0 = cmod ? (z / cmod) * ktn : 0;
    Ag += (long)c * sA;
    Bg += (long)c * sB;
    const int wm = (warp >> 1) * 64;
    const int wn = (warp & 1) * 64;

    float acc[4][8][4];
    #pragma unroll
    for (int i = 0; i < 4; i++)
        #pragma unroll
        for (int j = 0; j < 8; j++)
            #pragma unroll
            for (int v = 0; v < 4; v++) acc[i][j][v] = 0.f;

    auto load_half = [&](int st, int k0, int hf) {
        const uint32_t sa2 = sb + st * STG_SZ;
        const uint32_t sbm2 = sa2 + 16384;
        #pragma unroll
        for (int i = hf * 4; i < hf * 4 + 4; i++) {
            int id = i * 128 + tid;
            int row = id >> 3, cc2 = id & 7;
            uint32_t off = (uint32_t)row * 128 + (uint32_t)((cc2 ^ (row & 7)) << 4);
            cpasync16(sa2 + off, Ag + (long)(m0 + row) * lda + k0 + cc2 * 8);
            cpasync16(sbm2 + off, Bg + (long)(n0 + row) * ldb + k0 + cc2 * 8);
        }
    };

    #pragma unroll
    for (int s = 0; s < STAGES - 1; s++) {
        load_half(s, (kt0 + s) * 64, 0);
        load_half(s, (kt0 + s) * 64, 1);
        cpasync_commit();
    }

    int cs = 0, ns = STAGES - 1;
    for (int it = 0; it < ktn; it++) {
        if (it < ktn - 1) cpasync_wait<STAGES - 2>();
        else              cpasync_wait<0>();
        __syncthreads();
        const bool doload = (it + STAGES - 1) < ktn;
        const int k0n = (kt0 + it + STAGES - 1) * 64;

        const uint32_t sa = sb + cs * STG_SZ;
        const uint32_t sbm = sa + 16384;
        if (++cs == STAGES) cs = 0;

        uint32_t a[2][4][4], b[2][4][4];
        auto ldfrags = [&](int buf, int kk) {
            #pragma unroll
            for (int mi = 0; mi < 4; mi++) {
                int row = wm + mi * 16 + (lane & 15);
                int cc2 = kk * 2 + (lane >> 4);
                ldmx4(a[buf][mi], sa + row * 128 + ((cc2 ^ (row & 7)) << 4));
            }
            #pragma unroll
            for (int p = 0; p < 4; p++) {
                int row = wn + p * 16 + (lane & 7) + ((lane >> 4) << 3);
                int cc2 = kk * 2 + ((lane >> 3) & 1);
                ldmx4(b[buf][p], sbm + row * 128 + ((cc2 ^ (row & 7)) << 4));
            }
        };
        ldfrags(0, 0);
        #pragma unroll
        for (int kk = 0; kk < 4; kk++) {
            if (kk < 3) ldfrags((kk + 1) & 1, kk + 1);
            // interleave global prefetch while tensor pipe is busy
            if (doload && kk == 0) load_half(ns, k0n, 0);
            if (doload && kk == 1) { load_half(ns, k0n, 1); cpasync_commit(); }
            const int cur = kk & 1;
            #pragma unroll
            for (int mi = 0; mi < 4; mi++)
                #pragma unroll
                for (int p = 0; p < 4; p++) {
                    mma16(acc[mi][p * 2],     a[cur][mi], &b[cur][p][0]);
                    mma16(acc[mi][p * 2 + 1], a[cur][mi], &b[cur][p][2]);
                }
        }
        if (doload) { if (++ns == STAGES) ns = 0; }
    }

    // ---- store C ----
    #pragma unroll
    for (int mi = 0; mi < 4; mi++) {
        #pragma unroll
        for (int ni = 0; ni < 8; ni++) {
            int r0 = m0 + wm + mi * 16 + (lane >> 2);
            int c0 = n0 + wn + ni * 8 + (lane & 3) * 2;
            if (HALF) {
                __half* Ch = (__half*)Cp + (long)z * sC;
                *(__half2*)&Ch[(long)r0 * ldc + c0] =
                    __floats2half2_rn(acc[mi][ni][0], acc[mi][ni][1]);
                *(__half2*)&Ch[(long)(r0 + 8) * ldc + c0] =
                    __floats2half2_rn(acc[mi][ni][2], acc[mi][ni][3]);
            } else {
                float* Cf = (float*)Cp + (long)z * sC;
                float v0 = acc[mi][ni][0], v1 = acc[mi][ni][1];
                float v2 = acc[mi][ni][2], v3 = acc[mi][ni][3];
                if (EPI) {
                    float b0 = bias[c0], b1 = bias[c0 + 1];
                    v0 = fmaxf(v0 + b0, 0.f); v1 = fmaxf(v1 + b1, 0.f);
                    v2 = fmaxf(v2 + b0, 0.f); v3 = fmaxf(v3 + b1, 0.f);
                }
                float2 w0; w0.x = v0; w0.y = v1;
                float2 w1; w1.x = v2; w1.y = v3;
                *(float2*)&Cf[(long)r0 * ldc + c0]       = w0;
                *(float2*)&Cf[(long)(r0 + 8) * ldc + c0] = w1;
            }
        }
    }

    // ---- fused per-tile column sums (deterministic) ----
    if (COLSUM) {
        float* cs2 = (float*)smem;               // [2][128]
        __syncthreads();
        #pragma unroll
        for (int ni = 0; ni < 8; ni++) {
            #pragma unroll
            for (int j = 0; j < 2; j++) {
                float s = 0.f;
                #pragma unroll
                for (int mi = 0; mi < 4; mi++)
                    s += acc[mi][ni][j] + acc[mi][ni][2 + j];
                s += __shfl_xor_sync(0xFFFFFFFF, s, 4);
                s += __shfl_xor_sync(0xFFFFFFFF, s, 8);
                s += __shfl_xor_sync(0xFFFFFFFF, s, 16);
                if (lane < 4)
                    cs2[(wm >> 6) * 128 + wn + ni * 8 + (lane & 3) * 2 + j] = s;
            }
        }
        __syncthreads();
        if (tid < 128) {
            float tot = cs2[tid] + cs2[128 + tid];
            g_part[(long)c * 16 * NN + (long)blockIdx.y * NN + n0 + tid] = tot;
        }
    }
}

// ---------------- softmax over relations ----------------
__global__ void softmax_k(const float* __restrict__ W) {
    int t = threadIdx.x;
    if (t < 6) {
        const float* w = W + t * RR;
        float mx = w[0];
        #pragma unroll
        for (int r = 1; r < RR; r++) mx = fmaxf(mx, w[r]);
        float e[RR], s = 0.f;
        #pragma unroll
        for (int r = 0; r < RR; r++) { e[r] = expf(w[r] - mx); s += e[r]; }
        #pragma unroll
        for (int r = 0; r < RR; r++) g_F[t * RR + r] = e[r] / s;
    }
}

// ------- fused qcombine + transpose ----------
__global__ __launch_bounds__(256) void qcombine_t_k(const float* __restrict__ A) {
    __shared__ float t[RR][32][33];
    const int x0 = blockIdx.x * 32, y0 = blockIdx.y * 32;
    const int tx = threadIdx.x & 31, ty = threadIdx.x >> 5;
    #pragma unroll
    for (int r = 0; r < RR; r++)
        #pragma unroll
        for (int i = 0; i < 4; i++)
            t[r][ty + 8 * i][tx] = A[(long)r * NN * NN + (long)(y0 + ty + 8 * i) * NN + x0 + tx];
    __syncthreads();

    float f[6][RR];
    #pragma unroll
    for (int c = 0; c < 6; c++)
        #pragma unroll
        for (int r = 0; r < RR; r++) f[c][r] = g_F[c * RR + r];

    #pragma unroll
    for (int c = 0; c < 2; c++)
        #pragma unroll
        for (int i = 0; i < 4; i++) {
            int row = ty + 8 * i;
            float v = 0.f;
            #pragma unroll
            for (int r = 0; r < RR; r++) v = fmaf(f[c][r], t[r][row][tx], v);
            g_Q0f[(long)c * NN * NN + (long)(y0 + row) * NN + x0 + tx] = __float2half_rn(v);
        }
    #pragma unroll
    for (int c = 2; c < 6; c++) {
        __half* dst = (c < 4 ? g_Q1t : g_Q2t) + (long)(c & 1) * NN * NN;
        #pragma unroll
        for (int i = 0; i < 4; i++) {
            int rr = ty + 8 * i;
            float v = 0.f;
            #pragma unroll
            for (int r = 0; r < RR; r++) v = fmaf(f[c][r], t[r][tx][rr], v);
            dst[(long)(x0 + rr) * NN + y0 + tx] = __float2half_rn(v);
        }
    }
}

// ------- hW = h @ gcn_w, written transposed fp16: hWT[d][n] ----------
__global__ __launch_bounds__(256) void hw_t_k(const float* __restrict__ h,
                                              const float* __restrict__ w) {
    __shared__ float hs[32][257];
    const int n0 = blockIdx.x * 32, d0 = blockIdx.y * 32;
    const int tid = threadIdx.x;
    for (int idx = tid; idx < 32 * 256; idx += 256) {
        int n = idx >> 8, k = idx & 255;
        hs[n][k] = h[(long)(n0 + n) * DD + k];
    }
    __syncthreads();
    const int tx = tid & 31, ty = tid >> 5;
    float acc[4] = {0.f, 0.f, 0.f, 0.f};
    for (int k = 0; k < DD; k++) {
        float hv = hs[tx][k];
        #pragma unroll
        for (int i = 0; i < 4; i++)
            acc[i] = fmaf(hv, w[k * HD + d0 + ty + 8 * i], acc[i]);
    }
    #pragma unroll
    for (int i = 0; i < 4; i++)
        g_hWT[(long)(d0 + ty + 8 * i) * NN + n0 + tx] = __float2half_rn(acc[i]);
}

// ------- w1T[d'][k] = lin1_w[k][d'] fp16 ----------
__global__ __launch_bounds__(256) void w1t_k(const float* __restrict__ w) {
    __shared__ float t[32][33];
    const int x0 = blockIdx.x * 32;   // d' (0..127)
    const int y0 = blockIdx.y * 32;   // k (0..255)
    const int tx = threadIdx.x & 31, ty = threadIdx.x >> 5;
    #pragma unroll
    for (int i = 0; i < 4; i++)
        t[ty + 8 * i][tx] = w[(long)(y0 + ty + 8 * i) * HD + x0 + tx];
    __syncthreads();
    #pragma unroll
    for (int i = 0; i < 4; i++) {
        int rr = ty + 8 * i;
        g_w1T[(long)(x0 + rr) * (CC * HD) + y0 + tx] = __float2half_rn(t[tx][rr]);
    }
}

// ---- merged colsum+norm for stage 1: deg from g_part, Hf = norm(H16), half2 IO ----
__global__ __launch_bounds__(128) void normmid2_k(const __half* __restrict__ H) {
    const int chunk = blockIdx.x;                // 16 chunks of 256 columns
    const int c = (chunk * 256) / NN;
    const int col0 = (chunk * 256) % NN;
    const int t = threadIdx.x;
    const int m0 = col0 + 2 * t;
    const __half* Hc = H + (long)c * NN * NN;
    float inv[2];
    #pragma unroll
    for (int j = 0; j < 2; j++) {
        int m = m0 + j;
        float s = 0.f;
        #pragma unroll
        for (int p = 0; p < 16; p++)
            s += g_part[(long)c * 16 * NN + (long)p * NN + m];
        s -= __half2float(Hc[(long)m * NN + m]);
        inv[j] = (s > 0.f) ? 1.f / s : 0.f;
    }
    const int n0 = blockIdx.y * 64;
    for (int i = 0; i < 64; i++) {
        int n = n0 + i;
        long off = (long)c * NN * NN + (long)n * NN + m0;
        float2 vf = __half22float2(*(const __half2*)&g_H16[off]);
        float r0 = (n == m0)     ? 0.f : vf.x * inv[0];
        float r1 = (n == m0 + 1) ? 0.f : vf.y * inv[1];
        *(__half2*)&g_Hf[off] = __floats2half2_rn(r0, r1);
    }
}

// ---------------- colsum final for stage 2 (g_part -> g_deg) ----------------
__global__ __launch_bounds__(128) void colsum_final_k(const __half* __restrict__ H) {
    int idx = blockIdx.x * blockDim.x + threadIdx.x;
    if (idx >= CC * NN) return;
    int c = idx / NN, m = idx % NN;
    float s = 0.f;
    #pragma unroll
    for (int j = 0; j < 16; j++)
        s += g_part[(long)c * 16 * NN + (long)j * NN + m];
    s -= __half2float(H[(long)c * NN * NN + (long)m * NN + m]);
    g_deg[idx] = s;
}

// ------- final double norm fused with transpose -> fp16 HsT ----
__global__ __launch_bounds__(256) void norm_final_t_k(const __half* __restrict__ H) {
    __shared__ float t[32][33];
    const int c = blockIdx.z;
    const int x0 = blockIdx.x * 32, y0 = blockIdx.y * 32;
    const int tx = threadIdx.x & 31, ty = threadIdx.x >> 5;
    const float d1 = g_deg[c * NN + x0 + tx];
    const float inv1 = (d1 > 0.f) ? 1.f / d1 : 0.f;
    const float inv2 = (d1 > 0.f) ? 0.5f : 1.f;
    const __half* Hc = H + (long)c * NN * NN;
    #pragma unroll
    for (int i = 0; i < 4; i++) {
        int n = y0 + ty + 8 * i, m = x0 + tx;
        float v = __half2float(Hc[(long)n * NN + m]);
        v = (n == m) ? 1.f : v * inv1;
        t[ty + 8 * i][tx] = v * inv2;
    }
    __syncthreads();
    __half* dst = g_HsT + (long)c * NN * NN;
    #pragma unroll
    for (int i = 0; i < 4; i++) {
        int rr = ty + 8 * i;
        dst[(long)(x0 + rr) * NN + y0 + tx] = __float2half_rn(t[tx][rr]);
    }
}

// ---- split-K reduce + bias + relu -> fp16 concat Xcat[n][c*HD+d] ----
__global__ __launch_bounds__(256) void xreduce_k(const float* __restrict__ bias) {
    long i4 = ((long)blockIdx.x * blockDim.x + threadIdx.x) * 4;
    if (i4 >= (long)CC * NN * HD) return;
    float4 s = *(const float4*)&g_Xp[i4];
    #pragma unroll
    for (int ks = 1; ks < KS; ks++) {
        const float4 v = *(const float4*)&g_Xp[(long)ks * CC * NN * HD + i4];
        s.x += v.x; s.y += v.y; s.z += v.z; s.w += v.w;
    }
    const int c = (int)(i4 >> 18);               // NN*HD = 2^18
    const long rem = i4 & ((1L << 18) - 1);
    const int n = (int)(rem >> 7), d = (int)(rem & 127);
    s.x = fmaxf(s.x + bias[d],     0.f);
    s.y = fmaxf(s.y + bias[d + 1], 0.f);
    s.z = fmaxf(s.z + bias[d + 2], 0.f);
    s.w = fmaxf(s.w + bias[d + 3], 0.f);
    __half2* dst = (__half2*)&g_Xcat[(long)n * (CC * HD) + c * HD + d];
    dst[0] = __floats2half2_rn(s.x, s.y);
    dst[1] = __floats2half2_rn(s.z, s.w);
}

// ---------------- lin2: gather + X2[idx] @ W2 + b2 ----------------
__global__ __launch_bounds__(128) void lin2_k(const int* __restrict__ idx,
                                              const float* __restrict__ w,
                                              const float* __restrict__ b,
                                              float* __restrict__ y, int ncat) {
    int i = blockIdx.x * blockDim.x + threadIdx.x;
    if (i >= ncat * NCLS) return;
    int row = i / NCLS, j = i % NCLS;
    const float* x = g_X2 + (long)idx[row] * HD;
    float acc = b[j];
    #pragma unroll 8
    for (int k = 0; k < HD; k++)
        acc = fmaf(x[k], w[k * NCLS + j], acc);
    y[i] = acc;
}

// ---------------- launch ----------------
extern "C" void kernel_launch(void* const* d_in, const int* in_sizes, int n_in,
                              void* d_out, int out_size) {
    const float *A = 0, *h = 0, *W_conv = 0, *gcn_w = 0, *gcn_b = 0;
    const float *lin1_w = 0, *lin1_b = 0, *lin2_w = 0, *lin2_b = 0;
    const int* catidx = 0;
    int ncat = 0;
    for (int i = 0; i < n_in; i++) {
        int s = in_sizes[i];
        const void* p = d_in[i];
        if      (s == RR * NN * NN) A = (const float*)p;
        else if (s == NN * DD)      h = (const float*)p;
        else if (s == 3 * CC * RR)  W_conv = (const float*)p;
        else if (s == DD * HD) { if (!gcn_w) gcn_w = (const float*)p; else lin1_w = (const float*)p; }
        else if (s == HD)      { if (!gcn_b) gcn_b = (const float*)p; else lin1_b = (const float*)p; }
        else if (s == HD * NCLS) lin2_w = (const float*)p;
        else if (s == NCLS)      lin2_b = (const float*)p;
        else { catidx = (const int*)p; ncat = s; }
    }
    float* y = (float*)d_out;

    float *Xp, *X2;
    __half *Q0f, *Q1t, *Q2t, *H16, *Hf, *H216, *HsT, *hWT, *Xcat, *w1T;
    cudaGetSymbolAddress((void**)&Xp,   g_Xp);
    cudaGetSymbolAddress((void**)&X2,   g_X2);
    cudaGetSymbolAddress((void**)&Q0f,  g_Q0f);
    cudaGetSymbolAddress((void**)&Q1t,  g_Q1t);
    cudaGetSymbolAddress((void**)&Q2t,  g_Q2t);
    cudaGetSymbolAddress((void**)&H16,  g_H16);
    cudaGetSymbolAddress((void**)&Hf,   g_Hf);
    cudaGetSymbolAddress((void**)&H216, g_H216);
    cudaGetSymbolAddress((void**)&HsT,  g_HsT);
    cudaGetSymbolAddress((void**)&hWT,  g_hWT);
    cudaGetSymbolAddress((void**)&Xcat, g_Xcat);
    cudaGetSymbolAddress((void**)&w1T,  g_w1T);

    static int smem_set = 0;
    if (!smem_set) {
        cudaFuncSetAttribute((const void*)gemm16_k<true, true, false>,
                             cudaFuncAttributeMaxDynamicSharedMemorySize, SMEM16);
        cudaFuncSetAttribute((const void*)gemm16_k<false, false, false>,
                             cudaFuncAttributeMaxDynamicSharedMemorySize, SMEM16);
        cudaFuncSetAttribute((const void*)gemm16_k<false, false, true>,
                             cudaFuncAttributeMaxDynamicSharedMemorySize, SMEM16);
        smem_set = 1;
    }

    const long NNNN = (long)NN * NN;

    softmax_k<<<1, 32>>>(W_conv);
    qcombine_t_k<<<dim3(NN / 32, NN / 32), 256>>>(A);
    hw_t_k<<<dim3(NN / 32, HD / 32), 256>>>(h, gcn_w);
    w1t_k<<<dim3(HD / 32, CC * HD / 32), 256>>>(lin1_w);

    // GEMM1: H = Q0 @ Q1^T  (fp16 out + fused tile column sums)
    gemm16_k<true, true, false><<<dim3(16, 16, CC), 128, SMEM16>>>(
        Q0f, Q1t, H16, NN, NN, NN, NNNN, NNNN, NNNN, 0, 32, nullptr);
    // merged colsum + normalize -> Hf (fp16, half2 IO)
    normmid2_k<<<dim3(16, 32), 128>>>(H16);

    // GEMM2: H2 = Hn @ Q2^T  (fp16 out + fused tile column sums)
    gemm16_k<true, true, false><<<dim3(16, 16, CC), 128, SMEM16>>>(
        Hf, Q2t, H216, NN, NN, NN, NNNN, NNNN, NNNN, 0, 32, nullptr);
    colsum_final_k<<<CC * NN / 128, 128>>>(H216);
    norm_final_t_k<<<dim3(NN / 32, NN / 32, CC), 256>>>(H216);

    // X partials (split-K x4, ktn=8): Xp[ks*CC+c] = HsT[c] @ hWT^T over K-slice
    gemm16_k<false, false, false><<<dim3(HD / 128, NN / 128, CC * KS), 128, SMEM16>>>(
        HsT, hWT, Xp, NN, NN, HD, NNNN, 0, (long)NN * HD, CC, 32 / KS, nullptr);
    xreduce_k<<<(int)((long)CC * NN * HD / 4 / 256), 256>>>(gcn_b);

    // lin1: X2 = relu(Xcat @ w1T^T + b1)   (tensor cores, K=256)
    gemm16_k<false, false, true><<<dim3(1, NN / 128, 1), 128, SMEM16>>>(
        Xcat, w1T, X2, CC * HD, CC * HD, HD, 0, 0, 0, 0, (CC * HD) / 64, lin1_b);

    lin2_k<<<(ncat * NCLS + 127) / 128, 128>>>(catidx, lin2_w, lin2_b, y, ncat);
}